// round 10
// baseline (speedup 1.0000x reference)
#include <cuda_runtime.h>
#include <cuda_bf16.h>

#define NSAMP 128
#define FULL 0xffffffffu

// annealed NeuS alpha, single-divide formulation.
// pc=sig(prev*s), nc=sig(next*s); alpha=(pc-nc+eps)/(pc+eps)
//   = [(v-u) + eps(1+u)(1+v)] / [(1+v)(1+eps(1+u))],  u=e^{-prev*s}, v=e^{-next*s}
// args clamped to +-40: sigmoid is exactly saturated in f32 beyond ~17.3,
// and the clamp keeps every intermediate finite (u,v <= 2.4e17).
__device__ __forceinline__ float neus_alpha(float tc, float dist, float sdfv,
                                            float sv, float car) {
    float ic = -(fmaxf(0.5f - 0.5f * tc, 0.0f) * (1.0f - car) +
                 fmaxf(-tc, 0.0f) * car);
    float e = ic * dist * 0.5f;
    float xp = fminf(fmaxf((sdfv - e) * sv, -40.0f), 40.0f);
    float xn = fminf(fmaxf((sdfv + e) * sv, -40.0f), 40.0f);
    float u = __expf(-xp);
    float v = __expf(-xn);
    float up1 = 1.0f + u;
    float vp1 = 1.0f + v;
    float t   = 1e-5f * up1;
    float num = (v - u) + t * vp1;
    float den = vp1 * (1.0f + t);
    float a = __fdividef(num, den);
    return fminf(fmaxf(a, 0.0f), 1.0f);
}

// full per-ray pipeline AFTER the bulk loads have been issued.
// Takes the already-loaded registers; does alpha, scan, weights, reductions, stores.
__device__ __forceinline__ void process_ray(
    int ray, int lane,
    float4 s4, float4 z4,
    float4 g0, float4 g1, float4 g2,
    float4 c0, float4 c1, float4 c2,
    float rdx, float rdy, float rdz,
    float sv, float car,
    float* __restrict__ out_pixel, float* __restrict__ out_invd,
    float* __restrict__ out_w) {

    const float z_next = __shfl_down_sync(FULL, z4.x, 1);

    const float d0 = z4.y - z4.x;
    const float d1 = z4.z - z4.y;
    const float d2 = z4.w - z4.z;
    const float d3 = z_next - z4.w;            // garbage-but-finite on lane 31 (unused)

    const float tc0 = rdx * g0.x + rdy * g0.y + rdz * g0.z;
    const float tc1 = rdx * g0.w + rdy * g1.x + rdz * g1.y;
    const float tc2 = rdx * g1.z + rdy * g1.w + rdz * g2.x;
    const float tc3 = rdx * g2.y + rdy * g2.z + rdz * g2.w;

    float a0 = neus_alpha(tc0, d0, s4.x, sv, car);
    float a1 = neus_alpha(tc1, d1, s4.y, sv, car);
    float a2 = neus_alpha(tc2, d2, s4.z, sv, car);
    float a3 = neus_alpha(tc3, d3, s4.w, sv, car);
    if (lane == 31) a3 = 0.0f;                 // sample 127: appended zero alpha

    const float m0 = 1.0f - a0, m1 = 1.0f - a1, m2 = 1.0f - a2, m3 = 1.0f - a3;

    // warp exclusive prefix product of (1-alpha)
    float p = m0 * m1 * m2 * m3;
    #pragma unroll
    for (int off = 1; off < 32; off <<= 1) {
        float vsh = __shfl_up_sync(FULL, p, off);
        if (lane >= off) p *= vsh;
    }
    float excl = __shfl_up_sync(FULL, p, 1);
    if (lane == 0) excl = 1.0f;

    float run = excl;
    float w0 = a0 * run;  run *= m0;
    float w1 = a1 * run;  run *= m1;
    float w2 = a2 * run;  run *= m2;
    float w3 = a3 * run;                       // lane31: a3==0 -> w3==0
    if (lane == 0) w0 = 0.0f;                  // zero column prepended to T

    float px = w0 * c0.x + w1 * c0.w + w2 * c1.z + w3 * c2.y;
    float py = w0 * c0.y + w1 * c1.x + w2 * c1.w + w3 * c2.z;
    float pz = w0 * c0.z + w1 * c1.y + w2 * c2.x + w3 * c2.w;
    float iv = __fdividef(w0, z4.x) + __fdividef(w1, z4.y) +
               __fdividef(w2, z4.z) + __fdividef(w3, z4.w);

    #pragma unroll
    for (int off = 16; off; off >>= 1) {
        px += __shfl_xor_sync(FULL, px, off);
        py += __shfl_xor_sync(FULL, py, off);
        pz += __shfl_xor_sync(FULL, pz, off);
        iv += __shfl_xor_sync(FULL, iv, off);
    }

    float4 wout = make_float4(w0, w1, w2, w3);
    __stcs(reinterpret_cast<float4*>(out_w + (size_t)ray * NSAMP + lane * 4), wout);

    if (lane == 0) {
        out_pixel[ray * 3 + 0] = px;
        out_pixel[ray * 3 + 1] = py;
        out_pixel[ray * 3 + 2] = pz;
        out_invd[ray] = iv;
    }
}

__global__ __launch_bounds__(128, 4)
void neus_render_kernel(const float* __restrict__ sdf,
                        const float* __restrict__ color,
                        const float* __restrict__ zv,
                        const float* __restrict__ grad,
                        const float* __restrict__ rays_d,
                        const float* __restrict__ s_ptr,
                        const float* __restrict__ car_ptr,
                        float* __restrict__ out_pixel,
                        float* __restrict__ out_invd,
                        float* __restrict__ out_w,
                        int n_rays) {
    const int gtid = blockIdx.x * blockDim.x + threadIdx.x;
    const int warp = gtid >> 5;
    const int lane = gtid & 31;
    const int rayA = warp * 2;                 // two rays per warp
    const int rayB = rayA + 1;
    if (rayA >= n_rays) return;

    const int baseA = rayA * NSAMP + lane * 4;
    const int baseB = rayB * NSAMP + lane * 4;

    // ---- issue ALL 16 bulk LDG.128s (both rays) front-batched, evict-first ----
    const float4 sA = __ldcs(reinterpret_cast<const float4*>(sdf + baseA));
    const float4 sB = __ldcs(reinterpret_cast<const float4*>(sdf + baseB));
    const float4 zA = __ldcs(reinterpret_cast<const float4*>(zv  + baseA));
    const float4 zB = __ldcs(reinterpret_cast<const float4*>(zv  + baseB));

    const float4* gpA = reinterpret_cast<const float4*>(grad  + (size_t)rayA * (NSAMP * 3) + lane * 12);
    const float4* gpB = reinterpret_cast<const float4*>(grad  + (size_t)rayB * (NSAMP * 3) + lane * 12);
    const float4 gA0 = __ldcs(gpA + 0), gA1 = __ldcs(gpA + 1), gA2 = __ldcs(gpA + 2);
    const float4 gB0 = __ldcs(gpB + 0), gB1 = __ldcs(gpB + 1), gB2 = __ldcs(gpB + 2);

    const float4* cpA = reinterpret_cast<const float4*>(color + (size_t)rayA * (NSAMP * 3) + lane * 12);
    const float4* cpB = reinterpret_cast<const float4*>(color + (size_t)rayB * (NSAMP * 3) + lane * 12);
    const float4 cA0 = __ldcs(cpA + 0), cA1 = __ldcs(cpA + 1), cA2 = __ldcs(cpA + 2);
    const float4 cB0 = __ldcs(cpB + 0), cB1 = __ldcs(cpB + 1), cB2 = __ldcs(cpB + 2);

    const float sv  = __ldg(s_ptr);
    const float car = __ldg(car_ptr);
    const float rdxA = __ldg(rays_d + rayA * 3 + 0);
    const float rdyA = __ldg(rays_d + rayA * 3 + 1);
    const float rdzA = __ldg(rays_d + rayA * 3 + 2);
    const float rdxB = __ldg(rays_d + rayB * 3 + 0);
    const float rdyB = __ldg(rays_d + rayB * 3 + 1);
    const float rdzB = __ldg(rays_d + rayB * 3 + 2);

    // ---- ray A pipeline (B's loads still draining underneath) ----
    process_ray(rayA, lane, sA, zA, gA0, gA1, gA2, cA0, cA1, cA2,
                rdxA, rdyA, rdzA, sv, car, out_pixel, out_invd, out_w);

    // ---- ray B pipeline ----
    process_ray(rayB, lane, sB, zB, gB0, gB1, gB2, cB0, cB1, cB2,
                rdxB, rdyB, rdzB, sv, car, out_pixel, out_invd, out_w);
}

extern "C" void kernel_launch(void* const* d_in, const int* in_sizes, int n_in,
                              void* d_out, int out_size) {
    const float* sdf    = (const float*)d_in[0];   // [N,128]
    const float* color  = (const float*)d_in[1];   // [N,128,3]
    const float* zvals  = (const float*)d_in[2];   // [N,128]
    const float* grad   = (const float*)d_in[3];   // [N,128,3]
    const float* rays_d = (const float*)d_in[4];   // [N,3]
    const float* s      = (const float*)d_in[5];   // [1]
    const float* car    = (const float*)d_in[6];   // scalar

    const int n_rays = in_sizes[0] / NSAMP;

    float* out = (float*)d_out;
    float* out_pixel = out;                        // [N,3]
    float* out_invd  = out + (size_t)n_rays * 3;   // [N]
    float* out_w     = out + (size_t)n_rays * 4;   // [N,128]

    // 2 rays per warp, 4 warps per block
    const int threads = 128;
    const int warps_needed = (n_rays + 1) / 2;
    const int blocks = (warps_needed * 32 + threads - 1) / threads;
    neus_render_kernel<<<blocks, threads>>>(sdf, color, zvals, grad, rays_d,
                                            s, car, out_pixel, out_invd, out_w,
                                            n_rays);
}

// round 11
// speedup vs baseline: 1.1494x; 1.1494x over previous
#include <cuda_runtime.h>
#include <cuda_bf16.h>

#define NSAMP 128
#define FULL 0xffffffffu

// annealed NeuS alpha, single-divide formulation.
// pc=sig(prev*s), nc=sig(next*s); alpha=(pc-nc+eps)/(pc+eps)
//   = [(v-u) + eps(1+u)(1+v)] / [(1+v)(1+eps(1+u))],  u=e^{-prev*s}, v=e^{-next*s}
// args clamped to +-40: sigmoid is exactly saturated in f32 beyond ~17.3,
// and the clamp keeps every intermediate finite (u,v <= 2.4e17).
__device__ __forceinline__ float neus_alpha(float tc, float dist, float sdfv,
                                            float sv, float car) {
    float ic = -(fmaxf(0.5f - 0.5f * tc, 0.0f) * (1.0f - car) +
                 fmaxf(-tc, 0.0f) * car);
    float e = ic * dist * 0.5f;
    float xp = fminf(fmaxf((sdfv - e) * sv, -40.0f), 40.0f);
    float xn = fminf(fmaxf((sdfv + e) * sv, -40.0f), 40.0f);
    float u = __expf(-xp);
    float v = __expf(-xn);
    float up1 = 1.0f + u;
    float vp1 = 1.0f + v;
    float t   = 1e-5f * up1;
    float num = (v - u) + t * vp1;
    float den = vp1 * (1.0f + t);
    float a = __fdividef(num, den);
    return fminf(fmaxf(a, 0.0f), 1.0f);
}

__global__ __launch_bounds__(256, 6)
void neus_render_kernel(const float* __restrict__ sdf,
                        const float* __restrict__ color,
                        const float* __restrict__ zv,
                        const float* __restrict__ grad,
                        const float* __restrict__ rays_d,
                        const float* __restrict__ s_ptr,
                        const float* __restrict__ car_ptr,
                        float* __restrict__ out_pixel,
                        float* __restrict__ out_invd,
                        float* __restrict__ out_w,
                        int n_rays) {
    const int gtid = blockIdx.x * blockDim.x + threadIdx.x;
    const int ray  = gtid >> 5;
    const int lane = gtid & 31;
    if (ray >= n_rays) return;

    const int base = ray * NSAMP + lane * 4;   // this lane's 4 samples

    // ---- issue ALL bulk loads up front (8x LDG.128, evict-first) ----
    const float4 s4 = __ldcs(reinterpret_cast<const float4*>(sdf + base));
    const float4 z4 = __ldcs(reinterpret_cast<const float4*>(zv  + base));

    const float4* gp = reinterpret_cast<const float4*>(grad  + (size_t)ray * (NSAMP * 3) + lane * 12);
    const float4 g0 = __ldcs(gp + 0), g1 = __ldcs(gp + 1), g2 = __ldcs(gp + 2);
    const float4* cp = reinterpret_cast<const float4*>(color + (size_t)ray * (NSAMP * 3) + lane * 12);
    const float4 c0 = __ldcs(cp + 0), c1 = __ldcs(cp + 1), c2 = __ldcs(cp + 2);

    const float sv  = __ldg(s_ptr);
    const float car = __ldg(car_ptr);
    const float rdx = __ldg(rays_d + ray * 3 + 0);
    const float rdy = __ldg(rays_d + ray * 3 + 1);
    const float rdz = __ldg(rays_d + ray * 3 + 2);

    // next lane's first z (for dist of this lane's last sample)
    const float z_next = __shfl_down_sync(FULL, z4.x, 1);

    // ---- per-sample alpha ----
    const float d0 = z4.y - z4.x;
    const float d1 = z4.z - z4.y;
    const float d2 = z4.w - z4.z;
    const float d3 = z_next - z4.w;            // garbage-but-finite on lane 31 (unused)

    const float tc0 = rdx * g0.x + rdy * g0.y + rdz * g0.z;
    const float tc1 = rdx * g0.w + rdy * g1.x + rdz * g1.y;
    const float tc2 = rdx * g1.z + rdy * g1.w + rdz * g2.x;
    const float tc3 = rdx * g2.y + rdy * g2.z + rdz * g2.w;

    float a0 = neus_alpha(tc0, d0, s4.x, sv, car);
    float a1 = neus_alpha(tc1, d1, s4.y, sv, car);
    float a2 = neus_alpha(tc2, d2, s4.z, sv, car);
    float a3 = neus_alpha(tc3, d3, s4.w, sv, car);
    if (lane == 31) a3 = 0.0f;                 // sample 127: appended zero alpha

    const float m0 = 1.0f - a0, m1 = 1.0f - a1, m2 = 1.0f - a2, m3 = 1.0f - a3;

    // ---- warp exclusive prefix product of (1-alpha) ----
    float p = m0 * m1 * m2 * m3;
    #pragma unroll
    for (int off = 1; off < 32; off <<= 1) {
        float vsh = __shfl_up_sync(FULL, p, off);
        if (lane >= off) p *= vsh;
    }
    float excl = __shfl_up_sync(FULL, p, 1);
    if (lane == 0) excl = 1.0f;

    // ---- weights: w[j] = alpha[j] * prod_{i<j}(1-alpha[i]); w[0]=w[127]=0 ----
    float run = excl;
    float w0 = a0 * run;  run *= m0;
    float w1 = a1 * run;  run *= m1;
    float w2 = a2 * run;  run *= m2;
    float w3 = a3 * run;                       // lane31: a3==0 -> w3==0
    if (lane == 0) w0 = 0.0f;                  // zero column prepended to T

    // ---- accumulate pixel + invdepth ----
    float px = w0 * c0.x + w1 * c0.w + w2 * c1.z + w3 * c2.y;
    float py = w0 * c0.y + w1 * c1.x + w2 * c1.w + w3 * c2.z;
    float pz = w0 * c0.z + w1 * c1.y + w2 * c2.x + w3 * c2.w;
    float iv = __fdividef(w0, z4.x) + __fdividef(w1, z4.y) +
               __fdividef(w2, z4.z) + __fdividef(w3, z4.w);

    #pragma unroll
    for (int off = 16; off; off >>= 1) {
        px += __shfl_xor_sync(FULL, px, off);
        py += __shfl_xor_sync(FULL, py, off);
        pz += __shfl_xor_sync(FULL, pz, off);
        iv += __shfl_xor_sync(FULL, iv, off);
    }

    // ---- stores (streaming) ----
    float4 wout = make_float4(w0, w1, w2, w3);
    __stcs(reinterpret_cast<float4*>(out_w + (size_t)ray * NSAMP + lane * 4), wout);

    if (lane == 0) {
        out_pixel[ray * 3 + 0] = px;
        out_pixel[ray * 3 + 1] = py;
        out_pixel[ray * 3 + 2] = pz;
        out_invd[ray] = iv;
    }
}

extern "C" void kernel_launch(void* const* d_in, const int* in_sizes, int n_in,
                              void* d_out, int out_size) {
    const float* sdf    = (const float*)d_in[0];   // [N,128]
    const float* color  = (const float*)d_in[1];   // [N,128,3]
    const float* zvals  = (const float*)d_in[2];   // [N,128]
    const float* grad   = (const float*)d_in[3];   // [N,128,3]
    const float* rays_d = (const float*)d_in[4];   // [N,3]
    const float* s      = (const float*)d_in[5];   // [1]
    const float* car    = (const float*)d_in[6];   // scalar

    const int n_rays = in_sizes[0] / NSAMP;

    float* out = (float*)d_out;
    float* out_pixel = out;                        // [N,3]
    float* out_invd  = out + (size_t)n_rays * 3;   // [N]
    float* out_w     = out + (size_t)n_rays * 4;   // [N,128]

    const int threads = 256;                       // 8 warps = 8 rays / block
    const int blocks  = (n_rays * 32 + threads - 1) / threads;
    neus_render_kernel<<<blocks, threads>>>(sdf, color, zvals, grad, rays_d,
                                            s, car, out_pixel, out_invd, out_w,
                                            n_rays);
}